// round 8
// baseline (speedup 1.0000x reference)
#include <cuda_runtime.h>
#include <cuda_fp16.h>
#include <cstdint>
#include <cstddef>

// CustomConv 3x3 s1 p1: NHWC(32,56,56,128) x HWIO(3,3,128,256) + bias + ReLU.
// Implicit GEMM on mma.sync.m16n8k16 fp16 (fp32 accumulate).
//
// Round-8 changes vs round 7:
//  * BK=64 mainloop: each iteration covers a slab PAIR (same 3x3 tap), so
//    barriers/waits drop 36 -> 18 and each warp has 128 HMMAs between syncs.
//  * prepackA v2: 2 cin-slabs per thread -> 8 independent LDG.128 (more MLP).

#define H_ 56
#define W_ 56
#define HW 3136
#define COUT 256
#define NSLAB 36
#define NITER 18
#define NPIX (32 * HW)          // 100352

// fp16 A image, fragment-permuted per 32-cin granule: 25.7 MB.
__device__ __half g_Ah[(size_t)NPIX * 128];
// fp16 B, fragment-major: [cout-tile][slab][4096 halves = 8KB].
__device__ __half g_Bh[2][NSLAB][4096];

static __device__ __forceinline__ uint32_t smem_u32(const void* p) {
    uint32_t a;
    asm("{ .reg .u64 t; cvta.to.shared.u64 t, %1; cvt.u32.u64 %0, t; }"
        : "=r"(a) : "l"(p));
    return a;
}
static __device__ __forceinline__ void cpasync16(uint32_t dst, const void* src, int sz) {
    asm volatile("cp.async.cg.shared.global [%0], [%1], 16, %2;"
                 :: "r"(dst), "l"(src), "r"(sz) : "memory");
}

#define MMA_F16(d, a0, a1, a2, a3, b0, b1)                                         \
    asm volatile(                                                                  \
        "mma.sync.aligned.m16n8k16.row.col.f32.f16.f16.f32 "                       \
        "{%0,%1,%2,%3}, {%4,%5,%6,%7}, {%8,%9}, {%0,%1,%2,%3};"                    \
        : "+f"((d)[0]), "+f"((d)[1]), "+f"((d)[2]), "+f"((d)[3])                   \
        : "r"(a0), "r"(a1), "r"(a2), "r"(a3), "r"(b0), "r"(b1))

// ---------------- A prepack: fp32 -> fp16 with fragment permutation ----------------
// Per 32-cin slab, physical half p (tig = p>>3, w = p&7) holds
// logical cin = 2*tig + (w&1) + 8*((w>>1)&1) + 16*(w>>2).
// v2: two contiguous slabs (64 floats) per thread for deeper MLP.
__global__ void prepackA(const float* __restrict__ in) {
    const size_t u = (size_t)blockIdx.x * 256 + threadIdx.x;   // 200704 pairs
    const float* src = in + u * 64;
    float f[64];
    #pragma unroll
    for (int q = 0; q < 16; ++q) *(float4*)&f[q * 4] = ((const float4*)src)[q];
    __half h[64];
    #pragma unroll
    for (int sl = 0; sl < 2; ++sl)
        #pragma unroll
        for (int p = 0; p < 32; ++p) {
            const int tig = p >> 3, w = p & 7;
            const int k = 2 * tig + (w & 1) + 8 * ((w >> 1) & 1) + 16 * (w >> 2);
            h[sl * 32 + p] = __float2half(f[sl * 32 + k]);
        }
    uint4* dst = (uint4*)(g_Ah + u * 64);
    #pragma unroll
    for (int q = 0; q < 8; ++q) dst[q] = ((const uint4*)h)[q];
}

// ---------------- B prepack ----------------
// Half-index o in [0,4096): wn=o>>11, ks=(o>>10)&1, j=(o>>8)&3, lane=(o>>3)&31, e=o&7.
// g=lane>>2, tig=lane&3; nt=2*j+(e>>2); reg=(e>>1)&1.
// value = W[k = 2*tig + (e&1) + 8*reg + 16*ks][n = wn*64 + nt*8 + g]
__global__ void prepackB(const float* __restrict__ wgt) {
    const int s  = blockIdx.x;     // slab 0..35
    const int ct = blockIdx.y;     // cout tile 0..1
    const int t  = threadIdx.x;
    const int f  = s >> 2;         // tap
    const int cs = s & 3;          // cin slab
    __half* dst = &g_Bh[ct][s][0];
    #pragma unroll
    for (int q = 0; q < 16; ++q) {
        const int o    = t * 16 + q;
        const int wn   = o >> 11;
        const int ks   = (o >> 10) & 1;
        const int j    = (o >> 8) & 3;
        const int lane = (o >> 3) & 31;
        const int e    = o & 7;
        const int g    = lane >> 2, tig = lane & 3;
        const int nt   = 2 * j + (e >> 2);
        const int reg  = (e >> 1) & 1;
        const int k    = 2 * tig + (e & 1) + 8 * reg + 16 * ks;
        const int n    = wn * 64 + nt * 8 + g;
        dst[o] = __float2half(
            wgt[(size_t)(f * 128 + cs * 32 + k) * COUT + ct * 128 + n]);
    }
}

// ---------------- main kernel ----------------
// dyn smem: 3 stages x (A 16KB + B 16KB) = 98304 bytes; 2 CTAs/SM.
#define SMEM_BYTES 98304

__global__ __launch_bounds__(256, 2)
void conv_mma_f16(const float* __restrict__ bias, float* __restrict__ out) {
    extern __shared__ char smem[];
    const uint32_t sb = smem_u32(smem);
    const int tid  = threadIdx.x;
    const int lane = tid & 31;
    const int wid  = tid >> 5;
    const int g    = lane >> 2;
    const int tig  = lane & 3;
    const int wm   = wid & 3;        // warp M index -> 32 rows
    const int wn   = wid >> 2;       // warp N index -> 64 cols
    const int ntCTA   = blockIdx.x;
    const int pixBase = blockIdx.y * 128;

    // A-copy ownership: thread -> pixel row (tid>>1), half (tid&1) of the 128B
    // per-(pixel, 64-cin) record.
    const int rowA  = tid >> 1;
    const int halfA = tid & 1;
    const int pix = pixBase + rowA;
    const int n   = pix / HW;
    const int rm  = pix - n * HW;
    const int oh  = rm / W_;
    const int ow  = rm - oh * W_;

    float acc[2][8][4];
    #pragma unroll
    for (int mt = 0; mt < 2; ++mt)
        #pragma unroll
        for (int nt = 0; nt < 8; ++nt)
            #pragma unroll
            for (int e = 0; e < 4; ++e) acc[mt][nt][e] = 0.f;

    const char* Ag = (const char*)&g_Ah[0];
    const char* Bg = (const char*)&g_Bh[ntCTA][0][0];

    // Iteration t covers slabs (2t, 2t+1): tap f = t>>1, cin half csH = t&1.
    auto issue_copies = [&](int t, int stage) {
        const uint32_t Ab = sb + (uint32_t)stage * 32768u;
        const uint32_t Bb = Ab + 16384u;
        const int f = t >> 1, csH = t & 1;
        const int kh = f / 3, kw = f - kh * 3;
        const int ih = oh + kh - 1, iw = ow + kw - 1;
        const bool inb = (unsigned)ih < (unsigned)H_ && (unsigned)iw < (unsigned)W_;
        const char* srcA = inb
            ? Ag + ((size_t)((n * H_ + ih) * W_ + iw) * 256 + csH * 128 + halfA * 64)
            : Ag;
        const int sz = inb ? 16 : 0;
        const uint32_t dA = Ab + (uint32_t)(rowA * 128 + halfA * 64);
        #pragma unroll
        for (int q = 0; q < 4; ++q) cpasync16(dA + q * 16, srcA + q * 16, sz);
        const char* srcB = Bg + (size_t)t * 16384 + tid * 64;
        const uint32_t dB = Bb + (uint32_t)tid * 64;
        #pragma unroll
        for (int q = 0; q < 4; ++q) cpasync16(dB + q * 16, srcB + q * 16, 16);
    };

    // Prologue: iterations 0 and 1 into stages 0 and 1.
    issue_copies(0, 0);
    asm volatile("cp.async.commit_group;" ::: "memory");
    issue_copies(1, 1);
    asm volatile("cp.async.commit_group;" ::: "memory");

    const uint32_t bBase = (uint32_t)(wn * 4096 + lane * 16);

    // A row byte-bases: rows wm*32 + q*8 + g (q<2 -> mt0, q>=2 -> mt1), 128B rows.
    uint32_t aOff[4];
    #pragma unroll
    for (int q = 0; q < 4; ++q)
        aOff[q] = (uint32_t)((wm * 32 + q * 8 + g) * 128 + tig * 16);

    int stage = 0;
    #pragma unroll 1
    for (int t = 0; t < NITER; ++t) {
        asm volatile("cp.async.wait_group 1;" ::: "memory");
        __syncthreads();

        if (t + 2 < NITER) {
            int st2 = stage + 2; if (st2 >= 3) st2 -= 3;
            issue_copies(t + 2, st2);
        }
        asm volatile("cp.async.commit_group;" ::: "memory");

        const char* Abuf = smem + (size_t)stage * 32768;
        const char* Bbuf = Abuf + 16384;

        #pragma unroll
        for (int sh = 0; sh < 2; ++sh) {           // sub-slab (32 cins each)
            uint4 va[4];
            #pragma unroll
            for (int q = 0; q < 4; ++q)
                va[q] = *(const uint4*)(Abuf + aOff[q] + sh * 64);

            #pragma unroll
            for (int ks = 0; ks < 2; ++ks) {
                uint32_t b[8][2];
                #pragma unroll
                for (int j = 0; j < 4; ++j) {
                    const uint4 v = *(const uint4*)(Bbuf + sh * 8192 + bBase
                                                    + (uint32_t)(ks * 2048 + j * 512));
                    b[2 * j][0]     = v.x;
                    b[2 * j][1]     = v.y;
                    b[2 * j + 1][0] = v.z;
                    b[2 * j + 1][1] = v.w;
                }
                #pragma unroll
                for (int mt = 0; mt < 2; ++mt) {
                    const uint32_t a0 = ks ? va[2 * mt].z     : va[2 * mt].x;
                    const uint32_t a1 = ks ? va[2 * mt + 1].z : va[2 * mt + 1].x;
                    const uint32_t a2 = ks ? va[2 * mt].w     : va[2 * mt].y;
                    const uint32_t a3 = ks ? va[2 * mt + 1].w : va[2 * mt + 1].y;
                    #pragma unroll
                    for (int nt = 0; nt < 8; ++nt)
                        MMA_F16(acc[mt][nt], a0, a1, a2, a3, b[nt][0], b[nt][1]);
                }
            }
        }

        ++stage; if (stage >= 3) stage = 0;
    }

    // -------- epilogue: bias + ReLU, direct float2 stores --------
    #pragma unroll
    for (int nt = 0; nt < 8; ++nt) {
        const int col = ntCTA * 128 + wn * 64 + nt * 8 + tig * 2;
        const float2 bb = *(const float2*)&bias[col];
        #pragma unroll
        for (int mt = 0; mt < 2; ++mt) {
            const int r0 = pixBase + wm * 32 + mt * 16 + g;
            float2 v0, v1;
            v0.x = fmaxf(acc[mt][nt][0] + bb.x, 0.f);
            v0.y = fmaxf(acc[mt][nt][1] + bb.y, 0.f);
            v1.x = fmaxf(acc[mt][nt][2] + bb.x, 0.f);
            v1.y = fmaxf(acc[mt][nt][3] + bb.y, 0.f);
            *(float2*)&out[(size_t)r0 * COUT + col] = v0;
            *(float2*)&out[(size_t)(r0 + 8) * COUT + col] = v1;
        }
    }
}

extern "C" void kernel_launch(void* const* d_in, const int* in_sizes, int n_in,
                              void* d_out, int out_size) {
    const float* prev_a   = (const float*)d_in[0];   // [32,56,56,128]
    const float* filter_w = (const float*)d_in[1];   // [3,3,128,256]
    const float* filter_b = (const float*)d_in[2];   // [256]
    float* out = (float*)d_out;                      // [100352,256]

    prepackA<<<NPIX * 2 / 256, 256>>>(prev_a);       // 200704 slab-pairs
    prepackB<<<dim3(NSLAB, 2), 256>>>(filter_w);

    cudaFuncSetAttribute(conv_mma_f16, cudaFuncAttributeMaxDynamicSharedMemorySize,
                         SMEM_BYTES);
    conv_mma_f16<<<dim3(2, 784), 256, SMEM_BYTES>>>(filter_b, out);
}

// round 11
// speedup vs baseline: 1.1318x; 1.1318x over previous
#include <cuda_runtime.h>
#include <cuda_fp16.h>
#include <cstdint>
#include <cstddef>

// CustomConv 3x3 s1 p1: NHWC(32,56,56,128) x HWIO(3,3,128,256) + bias + ReLU.
// Implicit GEMM on mma.sync.m16n8k16 fp16 (fp32 accumulate).
//
// Round-11 (rounds 9/10 died to infra failures before running):
//  * main kernel: round-7 compute structure (best: 267us) + 4-stage cp.async
//    pipeline (wait_group 2) -- the still-unmeasured round-9 change.
//  * prepackA v3: one 16B output granule per thread (4x LDG.64 + 1x STG.128),
//    1.6M threads; v1 was wave-quantization/latency bound at 30% DRAM.

#define H_ 56
#define W_ 56
#define HW 3136
#define COUT 256
#define NSLAB 36
#define NPIX (32 * HW)          // 100352

// fp16 A image, fragment-permuted per 32-cin granule: 25.7 MB.
__device__ __half g_Ah[(size_t)NPIX * 128];
// fp16 B, fragment-major: [cout-tile][slab][4096 halves = 8KB].
__device__ __half g_Bh[2][NSLAB][4096];

static __device__ __forceinline__ uint32_t smem_u32(const void* p) {
    uint32_t a;
    asm("{ .reg .u64 t; cvta.to.shared.u64 t, %1; cvt.u32.u64 %0, t; }"
        : "=r"(a) : "l"(p));
    return a;
}
static __device__ __forceinline__ void cpasync16(uint32_t dst, const void* src, int sz) {
    asm volatile("cp.async.cg.shared.global [%0], [%1], 16, %2;"
                 :: "r"(dst), "l"(src), "r"(sz) : "memory");
}

#define MMA_F16(d, a0, a1, a2, a3, b0, b1)                                         \
    asm volatile(                                                                  \
        "mma.sync.aligned.m16n8k16.row.col.f32.f16.f16.f32 "                       \
        "{%0,%1,%2,%3}, {%4,%5,%6,%7}, {%8,%9}, {%0,%1,%2,%3};"                    \
        : "+f"((d)[0]), "+f"((d)[1]), "+f"((d)[2]), "+f"((d)[3])                   \
        : "r"(a0), "r"(a1), "r"(a2), "r"(a3), "r"(b0), "r"(b1))

// ---------------- A prepack (v3): fp32 -> fp16, granule-parallel ----------------
// Output granule gi covers halves g_Ah[slab*32 + tig*8 + w], slab = gi>>2,
// tig = gi&3, w = 0..7 holding logical cin = 2*tig + (w&1) + 8*((w>>1)&1)
// + 16*(w>>2)  ==  pairs at cins {2t, 2t+8, 2t+16, 2t+24}.
__global__ void prepackA(const float* __restrict__ in) {
    const size_t gi = (size_t)blockIdx.x * 256 + threadIdx.x;   // 1605632 granules
    const size_t slab = gi >> 2;
    const int tig = (int)(gi & 3);
    const float* src = in + slab * 32 + 2 * tig;
    const float2 f0 = *(const float2*)(src);
    const float2 f1 = *(const float2*)(src + 8);
    const float2 f2 = *(const float2*)(src + 16);
    const float2 f3 = *(const float2*)(src + 24);
    __half2 h[4];
    h[0] = __floats2half2_rn(f0.x, f0.y);
    h[1] = __floats2half2_rn(f1.x, f1.y);
    h[2] = __floats2half2_rn(f2.x, f2.y);
    h[3] = __floats2half2_rn(f3.x, f3.y);
    *(uint4*)(g_Ah + gi * 8) = *(const uint4*)h;
}

// ---------------- B prepack ----------------
// Half-index o in [0,4096): wn=o>>11, ks=(o>>10)&1, j=(o>>8)&3, lane=(o>>3)&31, e=o&7.
// g=lane>>2, tig=lane&3; nt=2*j+(e>>2); reg=(e>>1)&1.
// value = W[k = 2*tig + (e&1) + 8*reg + 16*ks][n = wn*64 + nt*8 + g]
__global__ void prepackB(const float* __restrict__ wgt) {
    const int s  = blockIdx.x;     // slab 0..35
    const int ct = blockIdx.y;     // cout tile 0..1
    const int t  = threadIdx.x;
    const int f  = s >> 2;         // tap
    const int cs = s & 3;          // cin slab
    __half* dst = &g_Bh[ct][s][0];
    #pragma unroll
    for (int q = 0; q < 16; ++q) {
        const int o    = t * 16 + q;
        const int wn   = o >> 11;
        const int ks   = (o >> 10) & 1;
        const int j    = (o >> 8) & 3;
        const int lane = (o >> 3) & 31;
        const int e    = o & 7;
        const int g    = lane >> 2, tig = lane & 3;
        const int nt   = 2 * j + (e >> 2);
        const int reg  = (e >> 1) & 1;
        const int k    = 2 * tig + (e & 1) + 8 * reg + 16 * ks;
        const int n    = wn * 64 + nt * 8 + g;
        dst[o] = __float2half(
            wgt[(size_t)(f * 128 + cs * 32 + k) * COUT + ct * 128 + n]);
    }
}

// ---------------- main kernel ----------------
// dyn smem: 4 stages x (A 8KB + B 8KB) = 65536 bytes; 2 CTAs/SM.
#define SMEM_BYTES 65536

__global__ __launch_bounds__(256, 2)
void conv_mma_f16(const float* __restrict__ bias, float* __restrict__ out) {
    extern __shared__ char smem[];
    const uint32_t sb = smem_u32(smem);
    const int tid  = threadIdx.x;
    const int lane = tid & 31;
    const int wid  = tid >> 5;
    const int g    = lane >> 2;
    const int tig  = lane & 3;
    const int wm   = wid & 3;        // warp M index -> 32 rows
    const int wn   = wid >> 2;       // warp N index -> 64 cols
    const int ntCTA   = blockIdx.x;
    const int pixBase = blockIdx.y * 128;

    // A-copy ownership: thread -> pixel row (tid>>1), half (tid&1) of 64B.
    const int rowA  = tid >> 1;
    const int halfA = tid & 1;
    const int pix = pixBase + rowA;
    const int n   = pix / HW;
    const int rm  = pix - n * HW;
    const int oh  = rm / W_;
    const int ow  = rm - oh * W_;

    float acc[2][8][4];
    #pragma unroll
    for (int mt = 0; mt < 2; ++mt)
        #pragma unroll
        for (int nt = 0; nt < 8; ++nt)
            #pragma unroll
            for (int e = 0; e < 4; ++e) acc[mt][nt][e] = 0.f;

    const char* Ag = (const char*)&g_Ah[0];
    const char* Bg = (const char*)&g_Bh[ntCTA][0][0];

    auto issue_copies = [&](int s, int stage) {
        const uint32_t Ab = sb + (uint32_t)stage * 16384u;
        const uint32_t Bb = Ab + 8192u;
        const int f = s >> 2, cs = s & 3;
        const int kh = f / 3, kw = f - kh * 3;
        const int ih = oh + kh - 1, iw = ow + kw - 1;
        const bool inb = (unsigned)ih < (unsigned)H_ && (unsigned)iw < (unsigned)W_;
        const char* srcA = inb
            ? Ag + ((size_t)((n * H_ + ih) * W_ + iw) * 256 + cs * 64 + halfA * 32)
            : Ag;
        const int sz = inb ? 16 : 0;
        const uint32_t dA = Ab + (uint32_t)(rowA * 64 + halfA * 32);
        cpasync16(dA,      srcA,      sz);
        cpasync16(dA + 16, srcA + 16, sz);
        const char* srcB = Bg + (size_t)s * 8192 + tid * 32;
        const uint32_t dB = Bb + (uint32_t)tid * 32;
        cpasync16(dB,      srcB,      16);
        cpasync16(dB + 16, srcB + 16, 16);
    };

    // Prologue: slabs 0..2 into stages 0..2.
    issue_copies(0, 0);
    asm volatile("cp.async.commit_group;" ::: "memory");
    issue_copies(1, 1);
    asm volatile("cp.async.commit_group;" ::: "memory");
    issue_copies(2, 2);
    asm volatile("cp.async.commit_group;" ::: "memory");

    const uint32_t bBase = (uint32_t)(wn * 4096 + lane * 16);

    // A row byte-bases: rows wm*32 + q*8 + g (q<2 -> mt0, q>=2 -> mt1), 64B rows.
    uint32_t aOff[4];
    #pragma unroll
    for (int q = 0; q < 4; ++q)
        aOff[q] = (uint32_t)((wm * 32 + q * 8 + g) * 64 + tig * 16);

    int stage = 0;
    #pragma unroll 1
    for (int s = 0; s < NSLAB; ++s) {
        asm volatile("cp.async.wait_group 2;" ::: "memory");
        __syncthreads();

        if (s + 3 < NSLAB) {
            int st3 = stage + 3; if (st3 >= 4) st3 -= 4;
            issue_copies(s + 3, st3);
        }
        asm volatile("cp.async.commit_group;" ::: "memory");

        const char* Abuf = smem + (size_t)stage * 16384;
        const char* Bbuf = Abuf + 8192;

        // One LDS.128 per row: regs = [ks0-klo, ks0-khi, ks1-klo, ks1-khi].
        uint4 va[4];
        #pragma unroll
        for (int q = 0; q < 4; ++q) va[q] = *(const uint4*)(Abuf + aOff[q]);

        #pragma unroll
        for (int ks = 0; ks < 2; ++ks) {
            uint32_t b[8][2];
            #pragma unroll
            for (int j = 0; j < 4; ++j) {
                const uint4 v =
                    *(const uint4*)(Bbuf + bBase + (uint32_t)(ks * 2048 + j * 512));
                b[2 * j][0]     = v.x;
                b[2 * j][1]     = v.y;
                b[2 * j + 1][0] = v.z;
                b[2 * j + 1][1] = v.w;
            }
            #pragma unroll
            for (int mt = 0; mt < 2; ++mt) {
                const uint32_t a0 = ks ? va[2 * mt].z     : va[2 * mt].x;
                const uint32_t a1 = ks ? va[2 * mt + 1].z : va[2 * mt + 1].x;
                const uint32_t a2 = ks ? va[2 * mt].w     : va[2 * mt].y;
                const uint32_t a3 = ks ? va[2 * mt + 1].w : va[2 * mt + 1].y;
                #pragma unroll
                for (int nt = 0; nt < 8; ++nt)
                    MMA_F16(acc[mt][nt], a0, a1, a2, a3, b[nt][0], b[nt][1]);
            }
        }

        ++stage; if (stage >= 4) stage = 0;
    }

    // -------- epilogue: bias + ReLU, direct float2 stores --------
    #pragma unroll
    for (int nt = 0; nt < 8; ++nt) {
        const int col = ntCTA * 128 + wn * 64 + nt * 8 + tig * 2;
        const float2 bb = *(const float2*)&bias[col];
        #pragma unroll
        for (int mt = 0; mt < 2; ++mt) {
            const int r0 = pixBase + wm * 32 + mt * 16 + g;
            float2 v0, v1;
            v0.x = fmaxf(acc[mt][nt][0] + bb.x, 0.f);
            v0.y = fmaxf(acc[mt][nt][1] + bb.y, 0.f);
            v1.x = fmaxf(acc[mt][nt][2] + bb.x, 0.f);
            v1.y = fmaxf(acc[mt][nt][3] + bb.y, 0.f);
            *(float2*)&out[(size_t)r0 * COUT + col] = v0;
            *(float2*)&out[(size_t)(r0 + 8) * COUT + col] = v1;
        }
    }
}

extern "C" void kernel_launch(void* const* d_in, const int* in_sizes, int n_in,
                              void* d_out, int out_size) {
    const float* prev_a   = (const float*)d_in[0];   // [32,56,56,128]
    const float* filter_w = (const float*)d_in[1];   // [3,3,128,256]
    const float* filter_b = (const float*)d_in[2];   // [256]
    float* out = (float*)d_out;                      // [100352,256]

    prepackA<<<NPIX * 128 / 8 / 256, 256>>>(prev_a); // 1605632 granules
    prepackB<<<dim3(NSLAB, 2), 256>>>(filter_w);

    cudaFuncSetAttribute(conv_mma_f16, cudaFuncAttributeMaxDynamicSharedMemorySize,
                         SMEM_BYTES);
    conv_mma_f16<<<dim3(2, 784), 256, SMEM_BYTES>>>(filter_b, out);
}